// round 12
// baseline (speedup 1.0000x reference)
#include <cuda_runtime.h>
#include <cuda_fp16.h>

#define K   8
#define D   16
#define NN  32
#define TT  200
#define BB  2048
#define LOG2PI 1.8378770664093453f
#define TPB 384
#define NW  12
#define GRID 296

// ---- word (4B) offsets; param image [0, W_PAR) identical in gmem & smem ----
#define W_EM   0       // -C fp16 rows: s*384 + n*12 + w (w=0..7 used)
#define W_DY   3072    // -A fp16 rows: s*192 + d*12 + w
#define W_EOF  4608    // -em_off f32: s*32 + n
#define W_EA2  4864    // exp(-2*em_ls) f32: s*32 + n
#define W_DOF  5120    // -dyn_off f32: s*16 + d
#define W_DA2  5248    // 1/dyn_scale^2 f32
#define W_INA  5376    // e^{-init_ls} f32
#define W_INB  5504    // -loc*e^{-init_ls} f32
#define W_TR   5632
#define W_C0   5696
#define W_CT   5704
#define W_PAR  5712
// dynamic-smem block-local regions (double buffered inputs)
#define W_OBS0 5712                 // obs f32, row stride 34 (200*34)
#define W_OBS1 12512
#define W_CONT0 19312               // cont f32 raw, contiguous 200*16
#define W_CONT1 22512
#define W_DS0  25712                // 200 ints
#define W_DS1  25912
#define W_Z    26112                // z fp16 pairs, stride 8 (200*8)
#define W_SSB  27712                // u8 state per t (byte-addressed)
#define W_TOFB 27768                // u8 rank->t
#define W_CNT  27824                // 12 warps x 8 states
#define W_TILE 27920                // <=24 tiles
#define W_NT   27944
#define W_RED  27945                // 12
#define W_TOT  27957                // 111828 bytes

#define SMEM_BYTES (W_TOT * 4)

__device__ __align__(16) unsigned int g_par[W_PAR];

#define H2(x) (*reinterpret_cast<const __half2*>(&(x)))

__device__ __forceinline__ void mma16816(float& d0, float& d1, float& d2, float& d3,
    unsigned a0, unsigned a1, unsigned a2, unsigned a3,
    unsigned b0, unsigned b1,
    float c0, float c1, float c2, float c3)
{
    asm("mma.sync.aligned.m16n8k16.row.col.f32.f16.f16.f32 "
        "{%0,%1,%2,%3}, {%4,%5,%6,%7}, {%8,%9}, {%10,%11,%12,%13};"
        : "=f"(d0), "=f"(d1), "=f"(d2), "=f"(d3)
        : "r"(a0), "r"(a1), "r"(a2), "r"(a3), "r"(b0), "r"(b1),
          "f"(c0), "f"(c1), "f"(c2), "f"(c3));
}

// ---------- prep (unchanged) ----------
__global__ __launch_bounds__(256)
void prep_kernel(const float* __restrict__ init_logits,
                 const float* __restrict__ init_locs,
                 const float* __restrict__ init_ls,
                 const float* __restrict__ trans_logits,
                 const float* __restrict__ dynM,
                 const float* __restrict__ dynOff,
                 const float* __restrict__ dynLS,
                 const float* __restrict__ emM,
                 const float* __restrict__ emOff,
                 const float* __restrict__ emLS)
{
    float* gf = reinterpret_cast<float*>(g_par);
    __half* gh = reinterpret_cast<__half*>(g_par);
    const int g = blockIdx.x * 256 + threadIdx.x;
    if (g < 4096) {
        int i = g, s = i >> 9, r = i & 511, n = r >> 4, d = r & 15;
        gh[(W_EM + s * 384 + n * 12) * 2 + d] = __float2half(-emM[i]);
    } else if (g < 6144) {
        int i = g - 4096, s = i >> 8, r = i & 255, dd = r >> 4, j = r & 15;
        gh[(W_DY + s * 192 + dd * 12) * 2 + j] = __float2half(-dynM[i]);
    } else if (g < 6400) {
        int i = g - 6144, s = i >> 5, n = i & 31;
        gf[W_EOF + s * 32 + n] = -emOff[i];
        gf[W_EA2 + s * 32 + n] = expf(-2.0f * emLS[i]);
    } else if (g < 6528) {
        int i = g - 6400, s = i >> 4, d = i & 15;
        gf[W_DOF + s * 16 + d] = -dynOff[i];
        float sc = dynLS[i];
        gf[W_DA2 + s * 16 + d] = 1.0f / (sc * sc);
        float ai = expf(-init_ls[i]);
        gf[W_INA + s * 16 + d] = ai;
        gf[W_INB + s * 16 + d] = -init_locs[i] * ai;
    } else if (g < 6592) {
        int i = g - 6528, sp = i >> 3;
        float m = -1e30f;
        for (int k = 0; k < K; k++) m = fmaxf(m, trans_logits[sp * K + k]);
        float sum = 0.0f;
        for (int k = 0; k < K; k++) sum += expf(trans_logits[sp * K + k] - m);
        gf[W_TR + i] = trans_logits[i] - m - logf(sum);
    } else if (g < 6600) {
        int s = g - 6592;
        float emc = -16.0f * LOG2PI;
        for (int n = 0; n < NN; n++) emc -= emLS[s * NN + n];
        float dync = -8.0f * LOG2PI;
        for (int d = 0; d < D; d++) dync -= logf(dynLS[s * D + d]);
        float initc = -8.0f * LOG2PI;
        for (int d = 0; d < D; d++) initc -= init_ls[s * D + d];
        float m = -1e30f;
        for (int k = 0; k < K; k++) m = fmaxf(m, init_logits[k]);
        float sum = 0.0f;
        for (int k = 0; k < K; k++) sum += expf(init_logits[k] - m);
        gf[W_C0 + s] = (init_logits[s] - m - logf(sum)) + initc + emc;
        gf[W_CT + s] = emc + dync;
    }
}

// ---------- cp.async prefetch of one batch into buffer p ----------
__device__ __forceinline__ void prefetch_batch(const float* __restrict__ obs,
                                               const float* __restrict__ cont,
                                               const int*   __restrict__ ds,
                                               int b, int p, unsigned sbase, int tid)
{
    // obs: 3200 float2 -> stride-34 f32 rows (8B cp.async)
    const float* osrc = obs + (size_t)b * (TT * NN);
    unsigned obase = sbase + (p ? W_OBS1 : W_OBS0) * 4u;
    for (int i = tid; i < TT * NN / 2; i += TPB) {
        unsigned dst = obase + ((unsigned)((i >> 4) * 34 + (i & 15) * 2)) * 4u;
        asm volatile("cp.async.ca.shared.global [%0], [%1], 8;" :: "r"(dst), "l"(osrc + i * 2));
    }
    // cont: 800 float4, contiguous
    const float* csrc = cont + (size_t)b * (TT * D);
    unsigned cbase = sbase + (p ? W_CONT1 : W_CONT0) * 4u;
    for (int i = tid; i < TT * D / 4; i += TPB) {
        asm volatile("cp.async.cg.shared.global [%0], [%1], 16;" :: "r"(cbase + i * 16u), "l"(csrc + i * 4));
    }
    // ds: 50 int4
    const int* dsrc = ds + (size_t)b * TT;
    unsigned dbase = sbase + (p ? W_DS1 : W_DS0) * 4u;
    if (tid < TT / 4)
        asm volatile("cp.async.cg.shared.global [%0], [%1], 16;" :: "r"(dbase + tid * 16u), "l"(dsrc + tid * 4));
    asm volatile("cp.async.commit_group;");
}

// ---------- main: persistent, double-buffered, MMA over sorted state tiles ----------
__global__ __launch_bounds__(TPB, 2)
void stage1_kernel(const int*   __restrict__ ds,
                   const float* __restrict__ cont,
                   const float* __restrict__ obs,
                   float*       __restrict__ out)
{
    extern __shared__ __align__(16) unsigned int sm[];
    float* smf = reinterpret_cast<float*>(sm);
    int* smi = reinterpret_cast<int*>(sm);
    unsigned char* smb = reinterpret_cast<unsigned char*>(sm);
    const unsigned sbase = (unsigned)__cvta_generic_to_shared(sm);
    const int tid = threadIdx.x;
    const int lane = tid & 31;
    const int warpid = tid >> 5;
    const bool active = tid < TT;
    const int g = lane >> 2;
    const int tig = lane & 3;

    // params image -> smem ONCE
    {
        const uint4* src = reinterpret_cast<const uint4*>(g_par);
        uint4* dst = reinterpret_cast<uint4*>(sm);
        #pragma unroll
        for (int i2 = 0; i2 < (W_PAR / 4 + TPB - 1) / TPB; i2++) {
            int i = tid + i2 * TPB;
            if (i < W_PAR / 4) dst[i] = src[i];
        }
    }
    // prime the pipeline: batch blockIdx.x into buffer 0
    prefetch_batch(obs, cont, ds, blockIdx.x, 0, sbase, tid);

    int it = 0;
    for (int b = blockIdx.x; b < BB; b += GRID, ++it) {
        const int p = it & 1;
        const int W_OBSp  = p ? W_OBS1 : W_OBS0;
        const int W_CONTp = p ? W_CONT1 : W_CONT0;
        const int W_DSp   = p ? W_DS1 : W_DS0;

        // prefetch next batch into other buffer
        int bn = b + GRID;
        if (bn >= BB) bn = b;
        prefetch_batch(obs, cont, ds, bn, p ^ 1, sbase, tid);
        asm volatile("cp.async.wait_group 1;");
        __syncthreads();

        // z fp16 pack from cont buffer (smem -> smem)
        for (int i = tid; i < TT * D / 4; i += TPB) {
            float4 v = *reinterpret_cast<const float4*>(smf + W_CONTp + i * 4);
            __half2 h0 = __floats2half2_rn(v.x, v.y);
            __half2 h1 = __floats2half2_rn(v.z, v.w);
            *reinterpret_cast<uint2*>(sm + W_Z + (i >> 2) * 8 + (i & 3) * 2) =
                make_uint2(*reinterpret_cast<unsigned*>(&h0), *reinterpret_cast<unsigned*>(&h1));
        }
        int s_raw = 8;
        if (active) {
            s_raw = smi[W_DSp + tid];
            smb[W_SSB * 4 + tid] = (unsigned char)s_raw;
        }
        if (tid < NW * 8) smi[W_CNT + tid] = 0;
        __syncthreads();

        unsigned mt = __match_any_sync(0xFFFFFFFFu, s_raw);
        int before = __popc(mt & ((1u << lane) - 1u));
        if (active && before == 0) smi[W_CNT + warpid * 8 + s_raw] = __popc(mt);
        __syncthreads();

        if (warpid == 0) {
            int tot = 0;
            if (lane < 8) {
                #pragma unroll
                for (int w = 0; w < NW; w++) tot += smi[W_CNT + w * 8 + lane];
            }
            int sc = tot;
            #pragma unroll
            for (int o = 1; o < 8; o <<= 1) {
                int v = __shfl_up_sync(0xFFFFFFFFu, sc, o);
                if (lane >= o) sc += v;
            }
            int base = sc - tot;
            if (lane < 8) {
                int run = base;
                #pragma unroll
                for (int w = 0; w < NW; w++) {
                    int c = smi[W_CNT + w * 8 + lane];
                    smi[W_CNT + w * 8 + lane] = run;
                    run += c;
                }
            }
            int ntk = (lane < 8) ? ((tot + 15) >> 4) : 0;
            int tsc = ntk;
            #pragma unroll
            for (int o = 1; o < 8; o <<= 1) {
                int v = __shfl_up_sync(0xFFFFFFFFu, tsc, o);
                if (lane >= o) tsc += v;
            }
            int tbase = tsc - ntk;
            if (lane < 8) {
                for (int j = 0; j < ntk; j++) {
                    int cnt = min(16, tot - 16 * j);
                    smi[W_TILE + tbase + j] = (lane << 13) | ((base + 16 * j) << 5) | cnt;
                }
                if (lane == 7) smi[W_NT] = tsc;
            }
        }
        __syncthreads();
        if (active) smb[W_TOFB * 4 + smi[W_CNT + warpid * 8 + s_raw] + before] = (unsigned char)tid;
        __syncthreads();

        const int nt = smi[W_NT];
        float part = 0.0f;

        for (int tile = warpid; tile < nt; tile += NW) {
            const int pk = smi[W_TILE + tile];
            const int cnt = pk & 31;
            const int rbase = (pk >> 5) & 255;
            const int s = pk >> 13;
            const bool v0 = g < cnt, v1 = g + 8 < cnt;
            const int t0 = smb[W_TOFB * 4 + rbase + (v0 ? g : 0)];
            const int t1 = smb[W_TOFB * 4 + rbase + (v1 ? g + 8 : 0)];

            unsigned a0 = sm[W_Z + t0 * 8 + tig];
            unsigned a1 = sm[W_Z + t1 * 8 + tig];
            unsigned a2 = sm[W_Z + t0 * 8 + tig + 4];
            unsigned a3 = sm[W_Z + t1 * 8 + tig + 4];

            // emission: 4 n-tiles; obs f32 from smem
            float acc0 = 0.0f, acc1 = 0.0f;
            #pragma unroll
            for (int ntl = 0; ntl < 4; ntl++) {
                const unsigned* Cb = sm + W_EM + s * 384 + (ntl * 8 + g) * 12;
                unsigned b0 = Cb[tig], b1 = Cb[tig + 4];
                float2 e = *reinterpret_cast<const float2*>(smf + W_EOF + s * 32 + ntl * 8 + 2 * tig);
                float2 q0 = *reinterpret_cast<const float2*>(smf + W_OBSp + t0 * 34 + ntl * 8 + 2 * tig);
                float2 q1 = *reinterpret_cast<const float2*>(smf + W_OBSp + t1 * 34 + ntl * 8 + 2 * tig);
                float d0, d1, d2, d3;
                mma16816(d0, d1, d2, d3, a0, a1, a2, a3, b0, b1,
                         q0.x + e.x, q0.y + e.y, q1.x + e.x, q1.y + e.y);
                float2 ea = *reinterpret_cast<const float2*>(smf + W_EA2 + s * 32 + ntl * 8 + 2 * tig);
                acc0 = fmaf(ea.x, d0 * d0, acc0); acc0 = fmaf(ea.y, d1 * d1, acc0);
                acc1 = fmaf(ea.x, d2 * d2, acc1); acc1 = fmaf(ea.y, d3 * d3, acc1);
            }

            // dynamics: 2 n-tiles
            int tp0 = (t0 > 0) ? t0 - 1 : 0;
            int tp1 = (t1 > 0) ? t1 - 1 : 0;
            unsigned p0 = sm[W_Z + tp0 * 8 + tig];
            unsigned p1 = sm[W_Z + tp1 * 8 + tig];
            unsigned p2 = sm[W_Z + tp0 * 8 + tig + 4];
            unsigned p3 = sm[W_Z + tp1 * 8 + tig + 4];
            float dac0 = 0.0f, dac1 = 0.0f;
            #pragma unroll
            for (int ntl = 0; ntl < 2; ntl++) {
                const unsigned* Ab = sm + W_DY + s * 192 + (ntl * 8 + g) * 12;
                unsigned b0 = Ab[tig], b1 = Ab[tig + 4];
                float2 df = *reinterpret_cast<const float2*>(smf + W_DOF + s * 16 + ntl * 8 + 2 * tig);
                float2 q0 = __half22float2(H2(sm[W_Z + t0 * 8 + ntl * 4 + tig]));
                float2 q1 = __half22float2(H2(sm[W_Z + t1 * 8 + ntl * 4 + tig]));
                float d0, d1, d2, d3;
                mma16816(d0, d1, d2, d3, p0, p1, p2, p3, b0, b1,
                         q0.x + df.x, q0.y + df.y, q1.x + df.x, q1.y + df.y);
                float2 da = *reinterpret_cast<const float2*>(smf + W_DA2 + s * 16 + ntl * 8 + 2 * tig);
                dac0 = fmaf(da.x, d0 * d0, dac0); dac0 = fmaf(da.y, d1 * d1, dac0);
                dac1 = fmaf(da.x, d2 * d2, dac1); dac1 = fmaf(da.y, d3 * d3, dac1);
            }

            float row0 = v0 ? (acc0 + ((t0 > 0) ? dac0 : 0.0f)) : 0.0f;
            float row1 = v1 ? (acc1 + ((t1 > 0) ? dac1 : 0.0f)) : 0.0f;
            row0 += __shfl_xor_sync(0xFFFFFFFFu, row0, 1);
            row0 += __shfl_xor_sync(0xFFFFFFFFu, row0, 2);
            row1 += __shfl_xor_sync(0xFFFFFFFFu, row1, 1);
            row1 += __shfl_xor_sync(0xFFFFFFFFu, row1, 2);

            if (tig == 0) {
                if (v0) {
                    float lp;
                    if (t0 > 0) lp = smf[W_CT + s] + smf[W_TR + smb[W_SSB * 4 + t0 - 1] * 8 + s];
                    else {
                        float iacc = 0.0f;
                        lp = smf[W_C0 + s];
                        #pragma unroll
                        for (int w = 0; w < 8; w++) {
                            float2 z = __half22float2(H2(sm[W_Z + w]));
                            float y0 = fmaf(z.x, smf[W_INA + s * 16 + 2 * w], smf[W_INB + s * 16 + 2 * w]);
                            float y1 = fmaf(z.y, smf[W_INA + s * 16 + 2 * w + 1], smf[W_INB + s * 16 + 2 * w + 1]);
                            iacc = fmaf(y0, y0, iacc); iacc = fmaf(y1, y1, iacc);
                        }
                        lp -= 0.5f * iacc;
                    }
                    part += lp - 0.5f * row0;
                }
                if (v1) {
                    float lp;
                    if (t1 > 0) lp = smf[W_CT + s] + smf[W_TR + smb[W_SSB * 4 + t1 - 1] * 8 + s];
                    else {
                        float iacc = 0.0f;
                        lp = smf[W_C0 + s];
                        #pragma unroll
                        for (int w = 0; w < 8; w++) {
                            float2 z = __half22float2(H2(sm[W_Z + w]));
                            float y0 = fmaf(z.x, smf[W_INA + s * 16 + 2 * w], smf[W_INB + s * 16 + 2 * w]);
                            float y1 = fmaf(z.y, smf[W_INA + s * 16 + 2 * w + 1], smf[W_INB + s * 16 + 2 * w + 1]);
                            iacc = fmaf(y0, y0, iacc); iacc = fmaf(y1, y1, iacc);
                        }
                        lp -= 0.5f * iacc;
                    }
                    part += lp - 0.5f * row1;
                }
            }
        }

        // block reduction (fixed assignment -> deterministic)
        #pragma unroll
        for (int o = 16; o > 0; o >>= 1) part += __shfl_xor_sync(0xFFFFFFFFu, part, o);
        if (lane == 0) smf[W_RED + warpid] = part;
        __syncthreads();
        if (tid == 0) {
            float sum = 0.0f;
            #pragma unroll
            for (int w = 0; w < NW; w++) sum += smf[W_RED + w];
            out[b] = sum;
        }
    }
    asm volatile("cp.async.wait_group 0;");
}

extern "C" void kernel_launch(void* const* d_in, const int* in_sizes, int n_in,
                              void* d_out, int out_size)
{
    const int*   ds    = (const int*)  d_in[0];
    const float* cont  = (const float*)d_in[1];
    const float* obs   = (const float*)d_in[2];
    const float* il    = (const float*)d_in[3];
    const float* iloc  = (const float*)d_in[4];
    const float* ils   = (const float*)d_in[5];
    const float* trl   = (const float*)d_in[6];
    const float* dynM  = (const float*)d_in[7];
    const float* dynO  = (const float*)d_in[8];
    const float* dynS  = (const float*)d_in[9];
    const float* emM   = (const float*)d_in[10];
    const float* emO   = (const float*)d_in[11];
    const float* emS   = (const float*)d_in[12];
    float* out = (float*)d_out;

    cudaFuncSetAttribute(stage1_kernel, cudaFuncAttributeMaxDynamicSharedMemorySize, SMEM_BYTES);
    prep_kernel<<<26, 256>>>(il, iloc, ils, trl, dynM, dynO, dynS, emM, emO, emS);
    stage1_kernel<<<GRID, TPB, SMEM_BYTES>>>(ds, cont, obs, out);
}

// round 13
// speedup vs baseline: 1.1943x; 1.1943x over previous
#include <cuda_runtime.h>
#include <cuda_fp16.h>

#define K   8
#define D   16
#define NN  32
#define TT  200
#define BB  2048
#define LOG2PI 1.8378770664093453f
#define TPB 256
#define GRID 592

// ---- word (4B) offsets; param image [0, W_PAR) identical in gmem & smem ----
#define W_EM   0       // -C fp16 rows: s*384 + n*12 + w (w=0..7 used)
#define W_DY   3072    // -A fp16 rows: s*192 + d*12 + w
#define W_EOF  4608    // -em_off f32: s*32 + n
#define W_EA2  4864    // exp(-2*em_ls) f32: s*32 + n
#define W_DOF  5120    // -dyn_off f32: s*16 + d
#define W_DA2  5248    // 1/dyn_scale^2 f32: s*16 + d
#define W_INA  5376    // e^{-init_ls} f32: s*16 + d
#define W_INB  5504    // -loc*e^{-init_ls} f32: s*16 + d
#define W_TR   5632    // 64
#define W_C0   5696    // 8
#define W_CT   5704    // 8
#define W_PAR  5712
// block-local smem
#define W_OBS  5712                 // obs fp16 pairs: t*20 + 2c
#define W_Z    (W_OBS + TT*20)      // 9712: z fp16 pairs: t*8 + dpair
#define W_SS   (W_Z + TT*8)         // 11312: raw state per t
#define W_TOF  (W_SS + 224)         // 11536: rank -> t
#define W_CNT  (W_TOF + 224)        // 11760: 8 warps x 8 states
#define W_TILE (W_CNT + 64)         // 11824: packed tiles (<= 20)
#define W_NT   (W_TILE + 24)        // 11848
#define W_B    11849                // current batch id (work stealing)
#define W_TOT  11852                // 47.4 KB

__device__ __align__(16) unsigned int g_par[W_PAR];
__device__ int g_ctr;

#define H2(x) (*reinterpret_cast<const __half2*>(&(x)))

__device__ __forceinline__ void mma16816(float& d0, float& d1, float& d2, float& d3,
    unsigned a0, unsigned a1, unsigned a2, unsigned a3,
    unsigned b0, unsigned b1,
    float c0, float c1, float c2, float c3)
{
    asm("mma.sync.aligned.m16n8k16.row.col.f32.f16.f16.f32 "
        "{%0,%1,%2,%3}, {%4,%5,%6,%7}, {%8,%9}, {%10,%11,%12,%13};"
        : "=f"(d0), "=f"(d1), "=f"(d2), "=f"(d3)
        : "r"(a0), "r"(a1), "r"(a2), "r"(a3), "r"(b0), "r"(b1),
          "f"(c0), "f"(c1), "f"(c2), "f"(c3));
}

// ---------- prep: one element per thread; also resets the work counter ----------
__global__ __launch_bounds__(256)
void prep_kernel(const float* __restrict__ init_logits,
                 const float* __restrict__ init_locs,
                 const float* __restrict__ init_ls,
                 const float* __restrict__ trans_logits,
                 const float* __restrict__ dynM,
                 const float* __restrict__ dynOff,
                 const float* __restrict__ dynLS,
                 const float* __restrict__ emM,
                 const float* __restrict__ emOff,
                 const float* __restrict__ emLS)
{
    float* gf = reinterpret_cast<float*>(g_par);
    __half* gh = reinterpret_cast<__half*>(g_par);
    const int g = blockIdx.x * 256 + threadIdx.x;
    if (g < 4096) {
        int i = g, s = i >> 9, r = i & 511, n = r >> 4, d = r & 15;
        gh[(W_EM + s * 384 + n * 12) * 2 + d] = __float2half(-emM[i]);
    } else if (g < 6144) {
        int i = g - 4096, s = i >> 8, r = i & 255, dd = r >> 4, j = r & 15;
        gh[(W_DY + s * 192 + dd * 12) * 2 + j] = __float2half(-dynM[i]);
    } else if (g < 6400) {
        int i = g - 6144, s = i >> 5, n = i & 31;
        gf[W_EOF + s * 32 + n] = -emOff[i];
        gf[W_EA2 + s * 32 + n] = expf(-2.0f * emLS[i]);
    } else if (g < 6528) {
        int i = g - 6400, s = i >> 4, d = i & 15;
        gf[W_DOF + s * 16 + d] = -dynOff[i];
        float sc = dynLS[i];
        gf[W_DA2 + s * 16 + d] = 1.0f / (sc * sc);
        float ai = expf(-init_ls[i]);
        gf[W_INA + s * 16 + d] = ai;
        gf[W_INB + s * 16 + d] = -init_locs[i] * ai;
    } else if (g < 6592) {
        int i = g - 6528, sp = i >> 3;
        float m = -1e30f;
        for (int k = 0; k < K; k++) m = fmaxf(m, trans_logits[sp * K + k]);
        float sum = 0.0f;
        for (int k = 0; k < K; k++) sum += expf(trans_logits[sp * K + k] - m);
        gf[W_TR + i] = trans_logits[i] - m - logf(sum);
    } else if (g < 6600) {
        int s = g - 6592;
        float emc = -16.0f * LOG2PI;
        for (int n = 0; n < NN; n++) emc -= emLS[s * NN + n];
        float dync = -8.0f * LOG2PI;
        for (int d = 0; d < D; d++) dync -= logf(dynLS[s * D + d]);
        float initc = -8.0f * LOG2PI;
        for (int d = 0; d < D; d++) initc -= init_ls[s * D + d];
        float m = -1e30f;
        for (int k = 0; k < K; k++) m = fmaxf(m, init_logits[k]);
        float sum = 0.0f;
        for (int k = 0; k < K; k++) sum += expf(init_logits[k] - m);
        gf[W_C0 + s] = (init_logits[s] - m - logf(sum)) + initc + emc;
        gf[W_CT + s] = emc + dync;
    } else if (g == 6600) {
        g_ctr = 0;
    }
}

// ---------- main: persistent work-stealing blocks; sorted state tiles via MMA ----------
__global__ __launch_bounds__(TPB, 4)
void stage1_kernel(const int*   __restrict__ ds,
                   const float* __restrict__ cont,
                   const float* __restrict__ obs,
                   float*       __restrict__ out)
{
    __shared__ __align__(16) unsigned int sm[W_TOT];
    __shared__ float sRed[TPB / 32];
    float* smf = reinterpret_cast<float*>(sm);
    int* smi = reinterpret_cast<int*>(sm);
    const int tid = threadIdx.x;
    const int lane = tid & 31;
    const int warpid = tid >> 5;
    const bool active = tid < TT;
    const int g = lane >> 2;
    const int tig = lane & 3;

    // params image -> smem ONCE per block
    {
        const uint4* src = reinterpret_cast<const uint4*>(g_par);
        uint4* dst = reinterpret_cast<uint4*>(sm);
        #pragma unroll
        for (int i2 = 0; i2 < (W_PAR / 4 + TPB - 1) / TPB; i2++) {
            int i = tid + i2 * TPB;
            if (i < W_PAR / 4) dst[i] = src[i];
        }
    }

    for (;;) {
        if (tid == 0) smi[W_B] = atomicAdd(&g_ctr, 1);
        __syncthreads();                 // broadcast b; also fences smem reuse
        const int b = smi[W_B];
        if (b >= BB) break;

        // ds first: sort's critical dependency issues before the staging burst
        int s_raw = 8;
        if (active) s_raw = ds[b * TT + tid];

        // obs -> smem fp16 pairs, row stride 20
        {
            const float4* src = reinterpret_cast<const float4*>(obs) + (size_t)b * (TT * NN / 4);
            #pragma unroll
            for (int i2 = 0; i2 < 7; i2++) {
                int i = tid + i2 * TPB;
                if (i < TT * NN / 4) {
                    float4 v = src[i];
                    int t = i >> 3, c = i & 7;
                    __half2 h0 = __floats2half2_rn(v.x, v.y);
                    __half2 h1 = __floats2half2_rn(v.z, v.w);
                    *reinterpret_cast<uint2*>(sm + W_OBS + t * 20 + c * 2) =
                        make_uint2(*reinterpret_cast<unsigned*>(&h0), *reinterpret_cast<unsigned*>(&h1));
                }
            }
        }
        // cont -> smem fp16 pairs, row stride 8
        {
            const float4* src = reinterpret_cast<const float4*>(cont) + (size_t)b * (TT * D / 4);
            #pragma unroll
            for (int i2 = 0; i2 < 4; i2++) {
                int i = tid + i2 * TPB;
                if (i < TT * D / 4) {
                    float4 v = src[i];
                    int t = i >> 2, q = i & 3;
                    __half2 h0 = __floats2half2_rn(v.x, v.y);
                    __half2 h1 = __floats2half2_rn(v.z, v.w);
                    *reinterpret_cast<uint2*>(sm + W_Z + t * 8 + q * 2) =
                        make_uint2(*reinterpret_cast<unsigned*>(&h0), *reinterpret_cast<unsigned*>(&h1));
                }
            }
        }
        if (active) smi[W_SS + tid] = s_raw;
        if (tid < 64) smi[W_CNT + tid] = 0;
        __syncthreads();

        // per-warp counts via match
        unsigned int mt = __match_any_sync(0xFFFFFFFFu, s_raw);
        int before = __popc(mt & ((1u << lane) - 1u));
        if (active && before == 0) smi[W_CNT + warpid * 8 + s_raw] = __popc(mt);
        __syncthreads();

        // parallel scan + tile build (warp 0)
        if (warpid == 0) {
            int tot = 0;
            if (lane < 8) {
                #pragma unroll
                for (int w = 0; w < 8; w++) tot += smi[W_CNT + w * 8 + lane];
            }
            int sc = tot;
            #pragma unroll
            for (int o = 1; o < 8; o <<= 1) {
                int v = __shfl_up_sync(0xFFFFFFFFu, sc, o);
                if (lane >= o) sc += v;
            }
            int base = sc - tot;
            if (lane < 8) {
                int run = base;
                #pragma unroll
                for (int w = 0; w < 8; w++) {
                    int c = smi[W_CNT + w * 8 + lane];
                    smi[W_CNT + w * 8 + lane] = run;
                    run += c;
                }
            }
            int ntk = (lane < 8) ? ((tot + 15) >> 4) : 0;
            int tsc = ntk;
            #pragma unroll
            for (int o = 1; o < 8; o <<= 1) {
                int v = __shfl_up_sync(0xFFFFFFFFu, tsc, o);
                if (lane >= o) tsc += v;
            }
            int tbase = tsc - ntk;
            if (lane < 8) {
                for (int j = 0; j < ntk; j++) {
                    int cnt = min(16, tot - 16 * j);
                    smi[W_TILE + tbase + j] = (lane << 13) | ((base + 16 * j) << 5) | cnt;
                }
                if (lane == 7) smi[W_NT] = tsc;
            }
        }
        __syncthreads();
        if (active) smi[W_TOF + smi[W_CNT + warpid * 8 + s_raw] + before] = tid;
        __syncthreads();

        const int nt = smi[W_NT];
        float part = 0.0f;

        for (int tile = warpid; tile < nt; tile += 8) {
            const int pk = smi[W_TILE + tile];
            const int cnt = pk & 31;
            const int rbase = (pk >> 5) & 255;
            const int s = pk >> 13;
            const bool v0 = g < cnt, v1 = g + 8 < cnt;
            const int t0 = smi[W_TOF + rbase + (v0 ? g : 0)];
            const int t1 = smi[W_TOF + rbase + (v1 ? g + 8 : 0)];

            unsigned a0 = sm[W_Z + t0 * 8 + tig];
            unsigned a1 = sm[W_Z + t1 * 8 + tig];
            unsigned a2 = sm[W_Z + t0 * 8 + tig + 4];
            unsigned a3 = sm[W_Z + t1 * 8 + tig + 4];

            // emission: 4 n-tiles
            float acc0 = 0.0f, acc1 = 0.0f;
            #pragma unroll
            for (int ntl = 0; ntl < 4; ntl++) {
                const unsigned* Cb = sm + W_EM + s * 384 + (ntl * 8 + g) * 12;
                unsigned b0 = Cb[tig], b1 = Cb[tig + 4];
                float2 e = *reinterpret_cast<const float2*>(smf + W_EOF + s * 32 + ntl * 8 + 2 * tig);
                float2 q0 = __half22float2(H2(sm[W_OBS + t0 * 20 + ntl * 4 + tig]));
                float2 q1 = __half22float2(H2(sm[W_OBS + t1 * 20 + ntl * 4 + tig]));
                float d0, d1, d2, d3;
                mma16816(d0, d1, d2, d3, a0, a1, a2, a3, b0, b1,
                         q0.x + e.x, q0.y + e.y, q1.x + e.x, q1.y + e.y);
                float2 ea = *reinterpret_cast<const float2*>(smf + W_EA2 + s * 32 + ntl * 8 + 2 * tig);
                acc0 = fmaf(ea.x, d0 * d0, acc0); acc0 = fmaf(ea.y, d1 * d1, acc0);
                acc1 = fmaf(ea.x, d2 * d2, acc1); acc1 = fmaf(ea.y, d3 * d3, acc1);
            }

            // dynamics: 2 n-tiles
            int tp0 = (t0 > 0) ? t0 - 1 : 0;
            int tp1 = (t1 > 0) ? t1 - 1 : 0;
            unsigned p0 = sm[W_Z + tp0 * 8 + tig];
            unsigned p1 = sm[W_Z + tp1 * 8 + tig];
            unsigned p2 = sm[W_Z + tp0 * 8 + tig + 4];
            unsigned p3 = sm[W_Z + tp1 * 8 + tig + 4];
            float dac0 = 0.0f, dac1 = 0.0f;
            #pragma unroll
            for (int ntl = 0; ntl < 2; ntl++) {
                const unsigned* Ab = sm + W_DY + s * 192 + (ntl * 8 + g) * 12;
                unsigned b0 = Ab[tig], b1 = Ab[tig + 4];
                float2 df = *reinterpret_cast<const float2*>(smf + W_DOF + s * 16 + ntl * 8 + 2 * tig);
                float2 q0 = __half22float2(H2(sm[W_Z + t0 * 8 + ntl * 4 + tig]));
                float2 q1 = __half22float2(H2(sm[W_Z + t1 * 8 + ntl * 4 + tig]));
                float d0, d1, d2, d3;
                mma16816(d0, d1, d2, d3, p0, p1, p2, p3, b0, b1,
                         q0.x + df.x, q0.y + df.y, q1.x + df.x, q1.y + df.y);
                float2 da = *reinterpret_cast<const float2*>(smf + W_DA2 + s * 16 + ntl * 8 + 2 * tig);
                dac0 = fmaf(da.x, d0 * d0, dac0); dac0 = fmaf(da.y, d1 * d1, dac0);
                dac1 = fmaf(da.x, d2 * d2, dac1); dac1 = fmaf(da.y, d3 * d3, dac1);
            }

            float row0 = v0 ? (acc0 + ((t0 > 0) ? dac0 : 0.0f)) : 0.0f;
            float row1 = v1 ? (acc1 + ((t1 > 0) ? dac1 : 0.0f)) : 0.0f;
            row0 += __shfl_xor_sync(0xFFFFFFFFu, row0, 1);
            row0 += __shfl_xor_sync(0xFFFFFFFFu, row0, 2);
            row1 += __shfl_xor_sync(0xFFFFFFFFu, row1, 1);
            row1 += __shfl_xor_sync(0xFFFFFFFFu, row1, 2);

            if (tig == 0) {
                if (v0) {
                    float lp;
                    if (t0 > 0) lp = smf[W_CT + s] + smf[W_TR + smi[W_SS + t0 - 1] * 8 + s];
                    else {
                        float iacc = 0.0f;
                        lp = smf[W_C0 + s];
                        #pragma unroll
                        for (int w = 0; w < 8; w++) {
                            float2 z = __half22float2(H2(sm[W_Z + w]));
                            float y0 = fmaf(z.x, smf[W_INA + s * 16 + 2 * w], smf[W_INB + s * 16 + 2 * w]);
                            float y1 = fmaf(z.y, smf[W_INA + s * 16 + 2 * w + 1], smf[W_INB + s * 16 + 2 * w + 1]);
                            iacc = fmaf(y0, y0, iacc); iacc = fmaf(y1, y1, iacc);
                        }
                        lp -= 0.5f * iacc;
                    }
                    part += lp - 0.5f * row0;
                }
                if (v1) {
                    float lp;
                    if (t1 > 0) lp = smf[W_CT + s] + smf[W_TR + smi[W_SS + t1 - 1] * 8 + s];
                    else {
                        float iacc = 0.0f;
                        lp = smf[W_C0 + s];
                        #pragma unroll
                        for (int w = 0; w < 8; w++) {
                            float2 z = __half22float2(H2(sm[W_Z + w]));
                            float y0 = fmaf(z.x, smf[W_INA + s * 16 + 2 * w], smf[W_INB + s * 16 + 2 * w]);
                            float y1 = fmaf(z.y, smf[W_INA + s * 16 + 2 * w + 1], smf[W_INB + s * 16 + 2 * w + 1]);
                            iacc = fmaf(y0, y0, iacc); iacc = fmaf(y1, y1, iacc);
                        }
                        lp -= 0.5f * iacc;
                    }
                    part += lp - 0.5f * row1;
                }
            }
        }

        // block reduction (fixed assignment -> deterministic)
        #pragma unroll
        for (int o = 16; o > 0; o >>= 1) part += __shfl_xor_sync(0xFFFFFFFFu, part, o);
        if (lane == 0) sRed[warpid] = part;
        __syncthreads();
        if (tid == 0) {
            float sum = 0.0f;
            #pragma unroll
            for (int w = 0; w < TPB / 32; w++) sum += sRed[w];
            out[b] = sum;
        }
    }
}

extern "C" void kernel_launch(void* const* d_in, const int* in_sizes, int n_in,
                              void* d_out, int out_size)
{
    const int*   ds    = (const int*)  d_in[0];
    const float* cont  = (const float*)d_in[1];
    const float* obs   = (const float*)d_in[2];
    const float* il    = (const float*)d_in[3];
    const float* iloc  = (const float*)d_in[4];
    const float* ils   = (const float*)d_in[5];
    const float* trl   = (const float*)d_in[6];
    const float* dynM  = (const float*)d_in[7];
    const float* dynO  = (const float*)d_in[8];
    const float* dynS  = (const float*)d_in[9];
    const float* emM   = (const float*)d_in[10];
    const float* emO   = (const float*)d_in[11];
    const float* emS   = (const float*)d_in[12];
    float* out = (float*)d_out;

    prep_kernel<<<26, 256>>>(il, iloc, ils, trl, dynM, dynO, dynS, emM, emO, emS);
    stage1_kernel<<<GRID, TPB>>>(ds, cont, obs, out);
}